// round 4
// baseline (speedup 1.0000x reference)
#include <cuda_runtime.h>
#include <cuda_bf16.h>
#include <mma.h>
#include <cstdint>

using namespace nvcuda;

#define N_NODES 100000
#define HIDDEN  128
#define N_EDGES 1600000

// ---------------- scratch (no allocations allowed -> __device__ globals) ----
__device__ float g_S [(size_t)N_NODES * HIDDEN];   // sigmoid(x[0] @ W^T + b)
__device__ float g_I [(size_t)N_NODES * HIDDEN];   // sigmoid(x[1] @ W^T + b)
__device__ float g_AI[(size_t)N_NODES * HIDDEN];   // segment_sum(I[cols], rows)
__device__ int   g_rows[N_EDGES];
__device__ int   g_cols[N_EDGES];
__device__ int   g_is64;

// ---------------- index dtype probe ----------------------------------------
// If the edge arrays are genuine int64, every value's hi-word is 0 and the
// int64 view of the first 512 entries lies in [0, N_NODES). If they are int32,
// the int64 view pairs two random indices -> the hi-word is itself a random
// index in [0,100000), essentially never 0 for all 512 samples.
// Deterministic for fixed input bytes -> graph/replay safe.
__global__ void detect_kernel(const void* rows) {
    const long long* p = (const long long*)rows;
    int ok64 = 1;
    for (int i = 0; i < 512; i++) {
        long long v = p[i];
        if (v < 0 || v >= N_NODES) { ok64 = 0; break; }
    }
    g_is64 = ok64;
}

__global__ void convert_kernel(const void* __restrict__ rows,
                               const void* __restrict__ cols) {
    int i = blockIdx.x * blockDim.x + threadIdx.x;
    if (i >= N_EDGES) return;
    if (g_is64) {
        g_rows[i] = (int)((const long long*)rows)[i];
        g_cols[i] = (int)((const long long*)cols)[i];
    } else {
        g_rows[i] = ((const int*)rows)[i];
        g_cols[i] = ((const int*)cols)[i];
    }
}

// ---------------- zero the accumulator -------------------------------------
__global__ void zero_kernel() {
    int i = blockIdx.x * blockDim.x + threadIdx.x;
    const int n4 = N_NODES * HIDDEN / 4;
    if (i < n4) ((float4*)g_AI)[i] = make_float4(0.f, 0.f, 0.f, 0.f);
}

// ---------------- tf32 wmma GEMM + sigmoid ---------------------------------
// out[s][n][o] = sigmoid( sum_h x[s][n][h] * W[o][h] + b[o] ), s in {0,1}.
// A = x (row-major, k=h), B = W viewed col-major (element (k=h, n=o) at
// W[o*128 + h]). Block: 128 threads (4 warps), tile 64 rows x 128 cols.
// W (64KB) stays L1/L2-resident; fragments load straight from global.
__global__ void __launch_bounds__(128)
gemm_kernel(const float* __restrict__ x, const float* __restrict__ W,
            const float* __restrict__ b) {
    const int s    = blockIdx.y;
    const int warp = threadIdx.x >> 5;
    const int row0 = blockIdx.x * 64 + warp * 16;

    __shared__ float biasTile[16 * HIDDEN];   // biasTile[r][o] = b[o]
    for (int i = threadIdx.x; i < 16 * HIDDEN; i += blockDim.x)
        biasTile[i] = b[i & (HIDDEN - 1)];
    __syncthreads();

    if (row0 >= N_NODES) return;

    const float* xs = x + ((size_t)s * N_NODES + row0) * HIDDEN;

    wmma::fragment<wmma::accumulator, 16, 16, 8, float> acc[8];
#pragma unroll
    for (int j = 0; j < 8; j++)
        wmma::load_matrix_sync(acc[j], biasTile + j * 16, HIDDEN,
                               wmma::mem_row_major);

    for (int k0 = 0; k0 < HIDDEN; k0 += 8) {
        wmma::fragment<wmma::matrix_a, 16, 16, 8, wmma::precision::tf32,
                       wmma::row_major> a;
        wmma::load_matrix_sync(a, xs + k0, HIDDEN);
#pragma unroll
        for (int t = 0; t < a.num_elements; t++)
            a.x[t] = wmma::__float_to_tf32(a.x[t]);
#pragma unroll
        for (int j = 0; j < 8; j++) {
            wmma::fragment<wmma::matrix_b, 16, 16, 8, wmma::precision::tf32,
                           wmma::col_major> bf;
            wmma::load_matrix_sync(bf, W + (size_t)(j * 16) * HIDDEN + k0,
                                   HIDDEN);
#pragma unroll
            for (int t = 0; t < bf.num_elements; t++)
                bf.x[t] = wmma::__float_to_tf32(bf.x[t]);
            wmma::mma_sync(acc[j], a, bf, acc[j]);
        }
    }

    float* out = (s == 0 ? g_S : g_I) + (size_t)row0 * HIDDEN;
#pragma unroll
    for (int j = 0; j < 8; j++) {
#pragma unroll
        for (int t = 0; t < acc[j].num_elements; t++) {
            float v = acc[j].x[t];
            acc[j].x[t] = 1.0f / (1.0f + __expf(-v));
        }
        wmma::store_matrix_sync(out + j * 16, acc[j], HIDDEN,
                                wmma::mem_row_major);
    }
}

// ---------------- edge scatter: AI[rows[e]] += I[cols[e]] -------------------
// One warp per edge; lane l moves float4 #l of the 128-float row.
// red.global.add.v4.f32 (sm_90+) quarters the L2 atomic op count vs scalar
// atomicAdd. Both g_I and g_AI (51.2 MB each) are L2-resident (126 MB L2),
// so this phase is LTS/atomic-throughput bound, not DRAM bound.
__global__ void __launch_bounds__(256)
scatter_kernel() {
    unsigned t = blockIdx.x * 256u + threadIdx.x;   // < 51.2M, fits 32-bit
    unsigned e = t >> 5;
    if (e >= N_EDGES) return;
    int lane = threadIdx.x & 31;
    int r = g_rows[e];
    int c = g_cols[e];
    float4 v = __ldg((const float4*)(g_I + (size_t)c * HIDDEN) + lane);
    float* dst = g_AI + (size_t)r * HIDDEN + lane * 4;
    asm volatile("red.global.add.v4.f32 [%0], {%1,%2,%3,%4};"
                 :: "l"(dst), "f"(v.x), "f"(v.y), "f"(v.z), "f"(v.w)
                 : "memory");
}

// ---------------- final elementwise combine --------------------------------
// dS = -beta*AI*S ; dI = -dS - gamma*I ; dR = gamma*I ; slab 3 = 0.
__global__ void __launch_bounds__(256)
final_kernel(const float* __restrict__ x, float* __restrict__ out) {
    int i = blockIdx.x * blockDim.x + threadIdx.x;   // over N_NODES*32 float4s
    const int NQ = N_NODES * 32;
    if (i >= NQ) return;
    int n = i >> 5;

    // beta = x[3,n,0], gamma = x[3,n,1]: adjacent -> one float2 load
    float2 bg = __ldg((const float2*)(x + ((size_t)3 * N_NODES + n) * HIDDEN));
    float beta = bg.x, gamma = bg.y;

    float4 ai = ((const float4*)g_AI)[i];
    float4 sv = ((const float4*)g_S)[i];
    float4 iv = ((const float4*)g_I)[i];

    float4 dS, dI, dR;
    dS.x = -beta * ai.x * sv.x;  dS.y = -beta * ai.y * sv.y;
    dS.z = -beta * ai.z * sv.z;  dS.w = -beta * ai.w * sv.w;
    dR.x = gamma * iv.x;  dR.y = gamma * iv.y;
    dR.z = gamma * iv.z;  dR.w = gamma * iv.w;
    dI.x = -dS.x - dR.x;  dI.y = -dS.y - dR.y;
    dI.z = -dS.z - dR.z;  dI.w = -dS.w - dR.w;

    float4* o = (float4*)out;
    o[i]          = dS;
    o[NQ + i]     = dI;
    o[2 * NQ + i] = dR;
    o[3 * NQ + i] = make_float4(0.f, 0.f, 0.f, 0.f);
}

// ---------------- launch ----------------------------------------------------
extern "C" void kernel_launch(void* const* d_in, const int* in_sizes, int n_in,
                              void* d_out, int out_size) {
    const float* x    = (const float*)d_in[0];
    const float* W    = (const float*)d_in[1];
    const float* b    = (const float*)d_in[2];
    const void*  rows = d_in[3];
    const void*  cols = d_in[4];
    float* out = (float*)d_out;

    detect_kernel<<<1, 1>>>(rows);
    convert_kernel<<<(N_EDGES + 255) / 256, 256>>>(rows, cols);
    zero_kernel<<<(N_NODES * HIDDEN / 4 + 255) / 256, 256>>>();

    dim3 gg((N_NODES + 63) / 64, 2);
    gemm_kernel<<<gg, 128>>>(x, W, b);

    // one warp per edge: N_EDGES*32 threads
    scatter_kernel<<<(N_EDGES * 32 + 255) / 256, 256>>>();

    final_kernel<<<(N_NODES * 32 + 255) / 256, 256>>>(x, out);
}

// round 6
// speedup vs baseline: 1.2673x; 1.2673x over previous
#include <cuda_runtime.h>
#include <cuda_bf16.h>
#include <mma.h>
#include <cstdint>

using namespace nvcuda;

#define N_NODES 100000
#define HIDDEN  128
#define N_EDGES 1600000

// GEMM tiling
#define GEMM_ROWS 128                  // rows per block
#define WLD       132                  // padded shared ld for W (breaks conflicts)
#define GEMM_SMEM ((128 * WLD + 16 * HIDDEN) * 4)

// ---------------- scratch (no allocations allowed -> __device__ globals) ----
__device__ float g_S [(size_t)N_NODES * HIDDEN];   // sigmoid(x[0] @ W^T + b)
__device__ float g_I [(size_t)N_NODES * HIDDEN];   // sigmoid(x[1] @ W^T + b)
__device__ float g_AI[(size_t)N_NODES * HIDDEN];   // segment_sum(I[cols], rows)
__device__ int   g_rows[N_EDGES];
__device__ int   g_cols[N_EDGES];
__device__ int   g_is64;

// ---------------- index dtype probe ----------------------------------------
// int64 data: hi-words are 0, so the int64 view of the first 512 entries lies
// in [0, N_NODES). int32 data: the int64 view pairs two random indices -> the
// hi-word is itself a random index, essentially never 0 for all 512 samples.
// Deterministic for fixed input bytes -> graph/replay safe.
__global__ void detect_kernel(const void* rows) {
    const long long* p = (const long long*)rows;
    int ok64 = 1;
    for (int i = 0; i < 512; i++) {
        long long v = p[i];
        if (v < 0 || v >= N_NODES) { ok64 = 0; break; }
    }
    g_is64 = ok64;
}

__global__ void convert_kernel(const void* __restrict__ rows,
                               const void* __restrict__ cols) {
    int i = blockIdx.x * blockDim.x + threadIdx.x;
    if (i >= N_EDGES) return;
    if (g_is64) {
        g_rows[i] = (int)((const long long*)rows)[i];
        g_cols[i] = (int)((const long long*)cols)[i];
    } else {
        g_rows[i] = ((const int*)rows)[i];
        g_cols[i] = ((const int*)cols)[i];
    }
}

// ---------------- zero the accumulator -------------------------------------
__global__ void zero_kernel() {
    int i = blockIdx.x * blockDim.x + threadIdx.x;
    const int n4 = N_NODES * HIDDEN / 4;
    if (i < n4) ((float4*)g_AI)[i] = make_float4(0.f, 0.f, 0.f, 0.f);
}

// ---------------- tf32 wmma GEMM + sigmoid (shared-staged W) ----------------
// out[s][n][o] = sigmoid( sum_h x[s][n][h] * W[o][h] + b[o] ), s in {0,1}.
// 256 threads (8 warps), tile 128 rows x 128 cols. W (64KB) is staged ONCE
// per block into dynamic shared memory, tf32-converted at store time, with
// ld=132 padding so col-major fragment loads don't serialize on one bank.
// B fragments come from shared; A fragments from global (each x element is
// read exactly once per block, coalesced 32B sectors). Bias is applied by
// initializing accumulators from a 16x128 broadcast tile.
__global__ void __launch_bounds__(256)
gemm_kernel(const float* __restrict__ x, const float* __restrict__ W,
            const float* __restrict__ b) {
    extern __shared__ float dyn[];
    float* smW = dyn;                      // [128][WLD]  smW[o][h] = tf32(W[o][h])
    float* smB = dyn + 128 * WLD;          // [16][128]   smB[r][o] = b[o]

    const int tid  = threadIdx.x;
    const int s    = blockIdx.y;
    const int warp = tid >> 5;
    const int row0 = blockIdx.x * GEMM_ROWS + warp * 16;

    for (int i = tid; i < HIDDEN * HIDDEN; i += 256)
        smW[(i >> 7) * WLD + (i & 127)] = wmma::__float_to_tf32(W[i]);
    for (int i = tid; i < 16 * HIDDEN; i += 256)
        smB[i] = b[i & (HIDDEN - 1)];
    __syncthreads();

    // 100000 % 16 == 0 -> every 16-row warp tile is fully in or fully out.
    if (row0 >= N_NODES) return;

    const float* xs = x + ((size_t)s * N_NODES + row0) * HIDDEN;

    wmma::fragment<wmma::accumulator, 16, 16, 8, float> acc[8];
#pragma unroll
    for (int j = 0; j < 8; j++)
        wmma::load_matrix_sync(acc[j], smB + j * 16, HIDDEN,
                               wmma::mem_row_major);

#pragma unroll 4
    for (int k0 = 0; k0 < HIDDEN; k0 += 8) {
        wmma::fragment<wmma::matrix_a, 16, 16, 8, wmma::precision::tf32,
                       wmma::row_major> a;
        wmma::load_matrix_sync(a, xs + k0, HIDDEN);
#pragma unroll
        for (int t = 0; t < a.num_elements; t++)
            a.x[t] = wmma::__float_to_tf32(a.x[t]);
#pragma unroll
        for (int j = 0; j < 8; j++) {
            wmma::fragment<wmma::matrix_b, 16, 16, 8, wmma::precision::tf32,
                           wmma::col_major> bf;
            // B(k=h, n=o) = smW[o*WLD + h]; base at (k0, o0=j*16), ld=WLD
            wmma::load_matrix_sync(bf, smW + (j * 16) * WLD + k0, WLD);
            wmma::mma_sync(acc[j], a, bf, acc[j]);
        }
    }

    float* out = (s == 0 ? g_S : g_I) + (size_t)row0 * HIDDEN;
#pragma unroll
    for (int j = 0; j < 8; j++) {
#pragma unroll
        for (int t = 0; t < acc[j].num_elements; t++) {
            float v = acc[j].x[t];
            acc[j].x[t] = 1.0f / (1.0f + __expf(-v));
        }
        wmma::store_matrix_sync(out + j * 16, acc[j], HIDDEN,
                                wmma::mem_row_major);
    }
}

// ---------------- edge scatter: AI[rows[e]] += I[cols[e]] -------------------
// One warp per edge; lane l moves float4 #l of the 128-float row.
// red.global.add.v4.f32 quarters the L2 atomic op count vs scalar atomicAdd.
__global__ void __launch_bounds__(256)
scatter_kernel() {
    unsigned t = blockIdx.x * 256u + threadIdx.x;   // < 51.2M, fits 32-bit
    unsigned e = t >> 5;
    if (e >= N_EDGES) return;
    int lane = threadIdx.x & 31;
    int r = g_rows[e];
    int c = g_cols[e];
    float4 v = __ldg((const float4*)(g_I + (size_t)c * HIDDEN) + lane);
    float* dst = g_AI + (size_t)r * HIDDEN + lane * 4;
    asm volatile("red.global.add.v4.f32 [%0], {%1,%2,%3,%4};"
                 :: "l"(dst), "f"(v.x), "f"(v.y), "f"(v.z), "f"(v.w)
                 : "memory");
}

// ---------------- final elementwise combine --------------------------------
// dS = -beta*AI*S ; dI = -dS - gamma*I ; dR = gamma*I ; slab 3 = 0.
__global__ void __launch_bounds__(256)
final_kernel(const float* __restrict__ x, float* __restrict__ out) {
    int i = blockIdx.x * blockDim.x + threadIdx.x;   // over N_NODES*32 float4s
    const int NQ = N_NODES * 32;
    if (i >= NQ) return;
    int n = i >> 5;

    float2 bg = __ldg((const float2*)(x + ((size_t)3 * N_NODES + n) * HIDDEN));
    float beta = bg.x, gamma = bg.y;

    float4 ai = ((const float4*)g_AI)[i];
    float4 sv = ((const float4*)g_S)[i];
    float4 iv = ((const float4*)g_I)[i];

    float4 dS, dI, dR;
    dS.x = -beta * ai.x * sv.x;  dS.y = -beta * ai.y * sv.y;
    dS.z = -beta * ai.z * sv.z;  dS.w = -beta * ai.w * sv.w;
    dR.x = gamma * iv.x;  dR.y = gamma * iv.y;
    dR.z = gamma * iv.z;  dR.w = gamma * iv.w;
    dI.x = -dS.x - dR.x;  dI.y = -dS.y - dR.y;
    dI.z = -dS.z - dR.z;  dI.w = -dS.w - dR.w;

    float4* o = (float4*)out;
    o[i]          = dS;
    o[NQ + i]     = dI;
    o[2 * NQ + i] = dR;
    o[3 * NQ + i] = make_float4(0.f, 0.f, 0.f, 0.f);
}

// ---------------- launch ----------------------------------------------------
extern "C" void kernel_launch(void* const* d_in, const int* in_sizes, int n_in,
                              void* d_out, int out_size) {
    const float* x    = (const float*)d_in[0];
    const float* W    = (const float*)d_in[1];
    const float* b    = (const float*)d_in[2];
    const void*  rows = d_in[3];
    const void*  cols = d_in[4];
    float* out = (float*)d_out;

    cudaFuncSetAttribute(gemm_kernel,
                         cudaFuncAttributeMaxDynamicSharedMemorySize,
                         GEMM_SMEM);

    detect_kernel<<<1, 1>>>(rows);
    convert_kernel<<<(N_EDGES + 255) / 256, 256>>>(rows, cols);
    zero_kernel<<<(N_NODES * HIDDEN / 4 + 255) / 256, 256>>>();

    dim3 gg((N_NODES + GEMM_ROWS - 1) / GEMM_ROWS, 2);
    gemm_kernel<<<gg, 256, GEMM_SMEM>>>(x, W, b);

    // one warp per edge: N_EDGES*32 threads
    scatter_kernel<<<(N_EDGES * 32 + 255) / 256, 256>>>();

    final_kernel<<<(N_NODES * 32 + 255) / 256, 256>>>(x, out);
}

// round 7
// speedup vs baseline: 2.0069x; 1.5835x over previous
#include <cuda_runtime.h>
#include <cuda_bf16.h>
#include <mma.h>
#include <cstdint>

using namespace nvcuda;

#define N_NODES 100000
#define HIDDEN  128
#define N_EDGES 1600000

// GEMM tiling
#define GEMM_ROWS 128
#define NTILES    ((N_NODES + GEMM_ROWS - 1) / GEMM_ROWS)   // 782
#define WLD       132                  // padded shared ld for W
#define GEMM_SMEM ((128 * WLD + 16 * HIDDEN) * 4)
#define GEMM_GRID 296                  // 2 blocks/SM x 148 SMs (occupancy limit)

// scan config
#define SCAN_CHUNK   1024
#define NSCAN_BLOCKS ((N_NODES + SCAN_CHUNK - 1) / SCAN_CHUNK)   // 98

// ---------------- scratch (no allocations -> __device__ globals) ------------
__device__ float g_S [(size_t)N_NODES * HIDDEN];
__device__ float g_I [(size_t)N_NODES * HIDDEN];
__device__ int   g_rows[N_EDGES];
__device__ int   g_cols[N_EDGES];
__device__ int   g_deg[N_NODES];        // per-row edge count
__device__ int   g_rowptr[N_NODES];     // exclusive prefix of g_deg
__device__ int   g_cursor[N_NODES];     // fill cursors (copy of rowptr)
__device__ int   g_edst[N_EDGES];       // cols grouped by row (CSR adj)
__device__ int   g_bsum[NSCAN_BLOCKS];
__device__ int   g_is64;

// ---------------- index dtype probe ----------------------------------------
// int64 data: hi-words are 0 -> int64 view of first 512 entries all lie in
// [0, N_NODES). int32 data: the int64 view pairs two random indices -> hi-word
// is itself a random index, essentially never 0 for all 512 samples.
// Deterministic for fixed input bytes -> graph/replay safe.
__global__ void detect_kernel(const void* rows) {
    const long long* p = (const long long*)rows;
    int ok64 = 1;
    for (int i = 0; i < 512; i++) {
        long long v = p[i];
        if (v < 0 || v >= N_NODES) { ok64 = 0; break; }
    }
    g_is64 = ok64;
}

__global__ void zero_deg_kernel() {
    int i = blockIdx.x * blockDim.x + threadIdx.x;
    if (i < N_NODES) g_deg[i] = 0;
}

// convert indices to int32 AND histogram the rows
__global__ void convert_hist_kernel(const void* __restrict__ rows,
                                    const void* __restrict__ cols) {
    int i = blockIdx.x * blockDim.x + threadIdx.x;
    if (i >= N_EDGES) return;
    int r, c;
    if (g_is64) {
        r = (int)((const long long*)rows)[i];
        c = (int)((const long long*)cols)[i];
    } else {
        r = ((const int*)rows)[i];
        c = ((const int*)cols)[i];
    }
    g_rows[i] = r;
    g_cols[i] = c;
    atomicAdd(&g_deg[r], 1);
}

// ---------------- exclusive scan of g_deg -> g_rowptr (3 kernels) -----------
__global__ void __launch_bounds__(256) scan1_kernel() {
    __shared__ int sums[256];
    int b = blockIdx.x, t = threadIdx.x;
    int base = b * SCAN_CHUNK + t * 4;
    int v[4];
#pragma unroll
    for (int k = 0; k < 4; k++)
        v[k] = (base + k < N_NODES) ? g_deg[base + k] : 0;
    int tsum = v[0] + v[1] + v[2] + v[3];
    sums[t] = tsum;
    __syncthreads();
    for (int off = 1; off < 256; off <<= 1) {
        int add = (t >= off) ? sums[t - off] : 0;
        __syncthreads();
        sums[t] += add;
        __syncthreads();
    }
    if (t == 255) g_bsum[b] = sums[255];
    int run = sums[t] - tsum;      // exclusive prefix of this thread
#pragma unroll
    for (int k = 0; k < 4; k++) {
        if (base + k < N_NODES) g_rowptr[base + k] = run;
        run += v[k];
    }
}

__global__ void __launch_bounds__(128) scan2_kernel() {
    __shared__ int s[128];
    int t = threadIdx.x;
    int orig = (t < NSCAN_BLOCKS) ? g_bsum[t] : 0;
    s[t] = orig;
    __syncthreads();
    for (int off = 1; off < 128; off <<= 1) {
        int add = (t >= off) ? s[t - off] : 0;
        __syncthreads();
        s[t] += add;
        __syncthreads();
    }
    if (t < NSCAN_BLOCKS) g_bsum[t] = s[t] - orig;   // exclusive
}

__global__ void scan3_kernel() {
    int i = blockIdx.x * blockDim.x + threadIdx.x;
    if (i >= N_NODES) return;
    int rp = g_rowptr[i] + g_bsum[i >> 10];
    g_rowptr[i] = rp;
    g_cursor[i] = rp;
}

// ---------------- CSR fill: group cols by row -------------------------------
__global__ void fill_kernel() {
    int e = blockIdx.x * blockDim.x + threadIdx.x;
    if (e >= N_EDGES) return;
    int r = g_rows[e];
    int pos = atomicAdd(&g_cursor[r], 1);
    g_edst[pos] = g_cols[e];
}

// ---------------- persistent tf32 wmma GEMM + sigmoid -----------------------
// W (64KB, tf32, ld=132) + bias tile staged ONCE per block; block then loops
// over 128-row tiles for both s=0 (S) and s=1 (I). No per-tile syncthreads:
// smW/smB are read-only after the initial barrier.
__global__ void __launch_bounds__(256)
gemm_kernel(const float* __restrict__ x, const float* __restrict__ W,
            const float* __restrict__ b) {
    extern __shared__ float dyn[];
    float* smW = dyn;                      // [128][WLD]
    float* smB = dyn + 128 * WLD;          // [16][128]

    const int tid  = threadIdx.x;
    const int warp = tid >> 5;

    for (int i = tid; i < HIDDEN * HIDDEN; i += 256)
        smW[(i >> 7) * WLD + (i & 127)] = wmma::__float_to_tf32(W[i]);
    for (int i = tid; i < 16 * HIDDEN; i += 256)
        smB[i] = b[i & (HIDDEN - 1)];
    __syncthreads();

    for (int tile = blockIdx.x; tile < 2 * NTILES; tile += gridDim.x) {
        const int s  = (tile >= NTILES) ? 1 : 0;
        const int t  = tile - s * NTILES;
        const int row0 = t * GEMM_ROWS + warp * 16;
        if (row0 >= N_NODES) continue;   // 100000 % 16 == 0: tiles all-in/out

        const float* xs = x + ((size_t)s * N_NODES + row0) * HIDDEN;

        wmma::fragment<wmma::accumulator, 16, 16, 8, float> acc[8];
#pragma unroll
        for (int j = 0; j < 8; j++)
            wmma::load_matrix_sync(acc[j], smB + j * 16, HIDDEN,
                                   wmma::mem_row_major);

#pragma unroll 4
        for (int k0 = 0; k0 < HIDDEN; k0 += 8) {
            wmma::fragment<wmma::matrix_a, 16, 16, 8, wmma::precision::tf32,
                           wmma::row_major> a;
            wmma::load_matrix_sync(a, xs + k0, HIDDEN);
#pragma unroll
            for (int q = 0; q < a.num_elements; q++)
                a.x[q] = wmma::__float_to_tf32(a.x[q]);
#pragma unroll
            for (int j = 0; j < 8; j++) {
                wmma::fragment<wmma::matrix_b, 16, 16, 8,
                               wmma::precision::tf32, wmma::col_major> bf;
                wmma::load_matrix_sync(bf, smW + (j * 16) * WLD + k0, WLD);
                wmma::mma_sync(acc[j], a, bf, acc[j]);
            }
        }

        float* outp = (s == 0 ? g_S : g_I) + (size_t)row0 * HIDDEN;
#pragma unroll
        for (int j = 0; j < 8; j++) {
#pragma unroll
            for (int q = 0; q < acc[j].num_elements; q++) {
                float v = acc[j].x[q];
                acc[j].x[q] = 1.0f / (1.0f + __expf(-v));
            }
            wmma::store_matrix_sync(outp + j * 16, acc[j], HIDDEN,
                                    wmma::mem_row_major);
        }
    }
}

// ---------------- fused CSR gather + epilogue -------------------------------
// One warp per row; lane l owns float4 #l of the 128-float feature vector.
// ai = sum over this row's adjacency of I[c]; then
// dS=-beta*ai*S, dI=-dS-gamma*I, dR=gamma*I, slab3=0 written directly.
// Replaces zero + atomic-scatter + final (one row write instead of ~16 REDs).
__global__ void __launch_bounds__(256)
gather_final_kernel(const float* __restrict__ x, float* __restrict__ out) {
    const int w    = blockIdx.x * 8 + (threadIdx.x >> 5);   // 100000 % 8 == 0
    const int lane = threadIdx.x & 31;

    const int start = g_rowptr[w];
    const int deg   = g_deg[w];
    const float4* I4 = (const float4*)g_I;

    float4 acc = make_float4(0.f, 0.f, 0.f, 0.f);
    int j = 0;
    for (; j + 4 <= deg; j += 4) {
        int c0 = __ldg(g_edst + start + j);
        int c1 = __ldg(g_edst + start + j + 1);
        int c2 = __ldg(g_edst + start + j + 2);
        int c3 = __ldg(g_edst + start + j + 3);
        float4 a0 = __ldg(I4 + (size_t)c0 * 32 + lane);
        float4 a1 = __ldg(I4 + (size_t)c1 * 32 + lane);
        float4 a2 = __ldg(I4 + (size_t)c2 * 32 + lane);
        float4 a3 = __ldg(I4 + (size_t)c3 * 32 + lane);
        acc.x += a0.x + a1.x + a2.x + a3.x;
        acc.y += a0.y + a1.y + a2.y + a3.y;
        acc.z += a0.z + a1.z + a2.z + a3.z;
        acc.w += a0.w + a1.w + a2.w + a3.w;
    }
    for (; j < deg; j++) {
        int c = __ldg(g_edst + start + j);
        float4 a = __ldg(I4 + (size_t)c * 32 + lane);
        acc.x += a.x; acc.y += a.y; acc.z += a.z; acc.w += a.w;
    }

    float2 bg = __ldg((const float2*)(x + ((size_t)3 * N_NODES + w) * HIDDEN));
    const float beta = bg.x, gamma = bg.y;

    const int idx = w * 32 + lane;
    float4 sv = ((const float4*)g_S)[idx];
    float4 iv = I4[idx];

    float4 dS, dI, dR;
    dS.x = -beta * acc.x * sv.x;  dS.y = -beta * acc.y * sv.y;
    dS.z = -beta * acc.z * sv.z;  dS.w = -beta * acc.w * sv.w;
    dR.x = gamma * iv.x;  dR.y = gamma * iv.y;
    dR.z = gamma * iv.z;  dR.w = gamma * iv.w;
    dI.x = -dS.x - dR.x;  dI.y = -dS.y - dR.y;
    dI.z = -dS.z - dR.z;  dI.w = -dS.w - dR.w;

    const int NQ = N_NODES * 32;
    float4* o = (float4*)out;
    o[idx]          = dS;
    o[NQ + idx]     = dI;
    o[2 * NQ + idx] = dR;
    o[3 * NQ + idx] = make_float4(0.f, 0.f, 0.f, 0.f);
}

// ---------------- launch ----------------------------------------------------
extern "C" void kernel_launch(void* const* d_in, const int* in_sizes, int n_in,
                              void* d_out, int out_size) {
    const float* x    = (const float*)d_in[0];
    const float* W    = (const float*)d_in[1];
    const float* b    = (const float*)d_in[2];
    const void*  rows = d_in[3];
    const void*  cols = d_in[4];
    float* out = (float*)d_out;

    cudaFuncSetAttribute(gemm_kernel,
                         cudaFuncAttributeMaxDynamicSharedMemorySize,
                         GEMM_SMEM);

    detect_kernel<<<1, 1>>>(rows);
    zero_deg_kernel<<<(N_NODES + 255) / 256, 256>>>();
    convert_hist_kernel<<<(N_EDGES + 255) / 256, 256>>>(rows, cols);

    scan1_kernel<<<NSCAN_BLOCKS, 256>>>();
    scan2_kernel<<<1, 128>>>();
    scan3_kernel<<<(N_NODES + 255) / 256, 256>>>();
    fill_kernel<<<(N_EDGES + 255) / 256, 256>>>();

    gemm_kernel<<<GEMM_GRID, 256, GEMM_SMEM>>>(x, W, b);

    gather_final_kernel<<<N_NODES / 8, 256>>>(x, out);
}